// round 1
// baseline (speedup 1.0000x reference)
#include <cuda_runtime.h>
#include <math.h>

#define EDIM 1024
#define TSEQ 2048
#define NTOK 4096      // B * T
#define FFD  4096
#define HDIM 64
#define LN_EPS 1e-5f

// ---------------- scratch (static device globals; no allocation) ----------------
__device__ float g_h [(size_t)NTOK*EDIM];
__device__ float g_q [(size_t)NTOK*EDIM];
__device__ float g_kb[(size_t)NTOK*EDIM];
__device__ float g_vb[(size_t)NTOK*EDIM];
__device__ float g_ao[(size_t)NTOK*EDIM];
__device__ float g_x1[(size_t)NTOK*EDIM];
__device__ float g_x2[(size_t)NTOK*EDIM];
__device__ float g_ff[(size_t)NTOK*FFD];

// ---------------- LayerNorm: one block per row of 1024 ----------------
__global__ __launch_bounds__(256)
void ln_kernel(const float* __restrict__ x, const float* __restrict__ gamma,
               const float* __restrict__ beta, float* __restrict__ out)
{
    const int row = blockIdx.x;
    const int t = threadIdx.x;                 // 256 threads, 4 floats each
    const float4 v = ((const float4*)(x + (size_t)row*EDIM))[t];
    float s  = v.x + v.y + v.z + v.w;
    float ss = v.x*v.x + v.y*v.y + v.z*v.z + v.w*v.w;
#pragma unroll
    for (int o = 16; o; o >>= 1){
        s  += __shfl_xor_sync(0xffffffffu, s,  o);
        ss += __shfl_xor_sync(0xffffffffu, ss, o);
    }
    __shared__ float sh_s[8], sh_ss[8];
    const int w = t >> 5, l = t & 31;
    if (l == 0){ sh_s[w] = s; sh_ss[w] = ss; }
    __syncthreads();
    if (w == 0){
        s  = (l < 8) ? sh_s[l]  : 0.f;
        ss = (l < 8) ? sh_ss[l] : 0.f;
#pragma unroll
        for (int o = 4; o; o >>= 1){
            s  += __shfl_xor_sync(0xffffffffu, s,  o);
            ss += __shfl_xor_sync(0xffffffffu, ss, o);
        }
        if (l == 0){ sh_s[0] = s; sh_ss[0] = ss; }
    }
    __syncthreads();
    const float mu   = sh_s[0] * (1.f/EDIM);
    const float var  = sh_ss[0] * (1.f/EDIM) - mu*mu;
    const float rstd = rsqrtf(var + LN_EPS);
    const float4 g4 = ((const float4*)gamma)[t];
    const float4 b4 = ((const float4*)beta)[t];
    float4 o4;
    o4.x = (v.x - mu)*rstd*g4.x + b4.x;
    o4.y = (v.y - mu)*rstd*g4.y + b4.y;
    o4.z = (v.z - mu)*rstd*g4.z + b4.z;
    o4.w = (v.w - mu)*rstd*g4.w + b4.w;
    ((float4*)(out + (size_t)row*EDIM))[t] = o4;
}

// ---------------- SGEMM: C[M,N] = A[M,K] @ W[K,N] + bias (+res)(+relu) --------
// 128x128 tile, BK=8, 256 threads, 8x8 per thread, double-buffered smem.
template<bool RELU, bool RES>
__global__ __launch_bounds__(256)
void sgemm_kernel(const float* __restrict__ A, const float* __restrict__ W,
                  const float* __restrict__ bias, const float* __restrict__ res,
                  float* __restrict__ C, int N, int K)
{
    __shared__ float As[2][8][128];
    __shared__ float Bs[2][8][128];

    const int tid = threadIdx.x;
    const int m0 = blockIdx.y * 128;
    const int n0 = blockIdx.x * 128;

    const int arow = tid >> 1;           // 0..127
    const int acol = (tid & 1) << 2;     // 0 or 4
    const int brow = tid >> 5;           // 0..7
    const int bcol = (tid & 31) << 2;    // 0..124

    const float* Ap = A + (size_t)(m0 + arow)*K + acol;
    const float* Wp = W + (size_t)brow*N + n0 + bcol;

    const int tn4 = (tid & 15) * 4;      // col split: tn4 and tn4+64
    const int tm4 = (tid >> 4) * 4;      // row split: tm4 and tm4+64

    float acc[8][8];
#pragma unroll
    for (int i = 0; i < 8; i++)
#pragma unroll
        for (int j = 0; j < 8; j++) acc[i][j] = 0.f;

    // prologue: stage 0
    {
        float4 a4 = *(const float4*)Ap;
        float4 b4 = *(const float4*)Wp;
        As[0][acol+0][arow] = a4.x;
        As[0][acol+1][arow] = a4.y;
        As[0][acol+2][arow] = a4.z;
        As[0][acol+3][arow] = a4.w;
        *(float4*)&Bs[0][brow][bcol] = b4;
    }

    const int KT = K >> 3;
    for (int kt = 0; kt < KT; ++kt){
        __syncthreads();
        const int buf = kt & 1;
        float4 na, nb;
        const bool more = (kt + 1 < KT);
        if (more){
            na = *(const float4*)(Ap + (size_t)(kt+1)*8);
            nb = *(const float4*)(Wp + (size_t)(kt+1)*8*N);
        }
#pragma unroll
        for (int k = 0; k < 8; k++){
            float a[8], b[8];
            *(float4*)&a[0] = *(const float4*)&As[buf][k][tm4];
            *(float4*)&a[4] = *(const float4*)&As[buf][k][tm4 + 64];
            *(float4*)&b[0] = *(const float4*)&Bs[buf][k][tn4];
            *(float4*)&b[4] = *(const float4*)&Bs[buf][k][tn4 + 64];
#pragma unroll
            for (int i = 0; i < 8; i++)
#pragma unroll
                for (int j = 0; j < 8; j++)
                    acc[i][j] = fmaf(a[i], b[j], acc[i][j]);
        }
        if (more){
            const int nxt = buf ^ 1;
            As[nxt][acol+0][arow] = na.x;
            As[nxt][acol+1][arow] = na.y;
            As[nxt][acol+2][arow] = na.z;
            As[nxt][acol+3][arow] = na.w;
            *(float4*)&Bs[nxt][brow][bcol] = nb;
        }
    }

    // epilogue
#pragma unroll
    for (int i = 0; i < 8; i++){
        const int r = (i < 4) ? (tm4 + i) : (64 + tm4 + i - 4);
        float* crow = C + (size_t)(m0 + r)*N + n0;
        const float* rrow = RES ? (res + (size_t)(m0 + r)*N + n0) : (const float*)0;
#pragma unroll
        for (int half = 0; half < 2; ++half){
            const int c = tn4 + half*64;
            const float4 bb = *(const float4*)&bias[n0 + c];
            float4 o;
            o.x = acc[i][half*4+0] + bb.x;
            o.y = acc[i][half*4+1] + bb.y;
            o.z = acc[i][half*4+2] + bb.z;
            o.w = acc[i][half*4+3] + bb.w;
            if (RELU){
                o.x = fmaxf(o.x, 0.f); o.y = fmaxf(o.y, 0.f);
                o.z = fmaxf(o.z, 0.f); o.w = fmaxf(o.w, 0.f);
            }
            if (RES){
                const float4 rv = *(const float4*)&rrow[c];
                o.x += rv.x; o.y += rv.y; o.z += rv.z; o.w += rv.w;
            }
            *(float4*)&crow[c] = o;
        }
    }
}

// ---------------- Flash attention, fp32 online softmax ----------------
// Block = 64 queries x 64 head-dims for one (b,h); loop over 64-key tiles.
// 256 threads, 4x4 register tiles for both S=QK^T and O+=P@V.
template<bool CAUSAL>
__global__ __launch_bounds__(256)
void attn_kernel(const float* __restrict__ Qg, const float* __restrict__ Kg,
                 const float* __restrict__ Vg, float* __restrict__ Og)
{
    const int P = 68;                      // row stride (floats), float4-aligned pad
    extern __shared__ float sm[];
    float* Qs   = sm;                      // 64*P
    float* Ks   = Qs + 64*P;
    float* Vs   = Ks + 64*P;
    float* Ss   = Vs + 64*P;
    float* mrow = Ss + 64*P;               // 64
    float* lrow = mrow + 64;               // 64
    float* arow = lrow + 64;               // 64

    const int tid = threadIdx.x;
    const int qt = blockIdx.x, h = blockIdx.y, b = blockIdx.z;
    const size_t base = (size_t)b*TSEQ*EDIM + (size_t)h*HDIM;

    const int tn4 = (tid & 15) * 4;
    const int tm4 = (tid >> 4) * 4;

    // load Q tile (64 rows x 64 dims)
#pragma unroll
    for (int i = 0; i < 4; i++){
        const int t4 = tid + i*256;
        const int r = t4 >> 4;
        const int c = (t4 & 15) << 2;
        *(float4*)&Qs[r*P + c] = *(const float4*)&Qg[base + (size_t)(qt*64 + r)*EDIM + c];
    }
    if (tid < 64){ mrow[tid] = -1e30f; lrow[tid] = 0.f; }

    float acc[4][4];
#pragma unroll
    for (int i = 0; i < 4; i++)
#pragma unroll
        for (int j = 0; j < 4; j++) acc[i][j] = 0.f;

    const int nkt = CAUSAL ? (qt + 1) : (TSEQ/64);

    for (int kt = 0; kt < nkt; ++kt){
        __syncthreads();                    // prior O-phase done; Q visible on iter 0
#pragma unroll
        for (int i = 0; i < 4; i++){
            const int t4 = tid + i*256;
            const int r = t4 >> 4;
            const int c = (t4 & 15) << 2;
            const size_t go = base + (size_t)(kt*64 + r)*EDIM + c;
            *(float4*)&Ks[r*P + c] = *(const float4*)&Kg[go];
            *(float4*)&Vs[r*P + c] = *(const float4*)&Vg[go];
        }
        __syncthreads();

        // S = (Q K^T) / 8
        float s[4][4];
#pragma unroll
        for (int i = 0; i < 4; i++)
#pragma unroll
            for (int j = 0; j < 4; j++) s[i][j] = 0.f;
#pragma unroll
        for (int d = 0; d < HDIM; d += 4){
            float qb[4][4], kb[4][4];
#pragma unroll
            for (int i = 0; i < 4; i++)
                *(float4*)qb[i] = *(const float4*)&Qs[(tm4+i)*P + d];
#pragma unroll
            for (int j = 0; j < 4; j++)
                *(float4*)kb[j] = *(const float4*)&Ks[(tn4+j)*P + d];
#pragma unroll
            for (int i = 0; i < 4; i++)
#pragma unroll
                for (int j = 0; j < 4; j++)
                    s[i][j] += qb[i][0]*kb[j][0] + qb[i][1]*kb[j][1]
                             + qb[i][2]*kb[j][2] + qb[i][3]*kb[j][3];
        }
#pragma unroll
        for (int i = 0; i < 4; i++)
#pragma unroll
            for (int j = 0; j < 4; j++){
                float v = s[i][j] * 0.125f;
                if (CAUSAL && (kt*64 + tn4 + j) > (qt*64 + tm4 + i)) v = -1e30f;
                Ss[(tm4+i)*P + tn4 + j] = v;
            }
        __syncthreads();

        // online softmax: 4 lanes per row (quad = adjacent lanes)
        {
            const int r = tid >> 2;
            const int g = tid & 3;
            float* srow = &Ss[r*P + g*16];
            const float mold = mrow[r];
            float mx = -1e30f;
#pragma unroll
            for (int c = 0; c < 16; c++) mx = fmaxf(mx, srow[c]);
            mx = fmaxf(mx, __shfl_xor_sync(0xffffffffu, mx, 1));
            mx = fmaxf(mx, __shfl_xor_sync(0xffffffffu, mx, 2));
            const float mnew = fmaxf(mold, mx);
            float sum = 0.f;
#pragma unroll
            for (int c = 0; c < 16; c++){
                const float p = __expf(srow[c] - mnew);
                srow[c] = p;
                sum += p;
            }
            sum += __shfl_xor_sync(0xffffffffu, sum, 1);
            sum += __shfl_xor_sync(0xffffffffu, sum, 2);
            if (g == 0){
                const float al = __expf(mold - mnew);
                mrow[r] = mnew;
                lrow[r] = lrow[r]*al + sum;
                arow[r] = al;
            }
        }
        __syncthreads();

        // O = O*alpha + P @ V
        float al[4];
#pragma unroll
        for (int i = 0; i < 4; i++) al[i] = arow[tm4 + i];
#pragma unroll
        for (int i = 0; i < 4; i++)
#pragma unroll
            for (int j = 0; j < 4; j++) acc[i][j] *= al[i];
#pragma unroll
        for (int c = 0; c < 64; c += 4){
            float pb[4][4], vb[4][4];
#pragma unroll
            for (int i = 0; i < 4; i++)
                *(float4*)pb[i] = *(const float4*)&Ss[(tm4+i)*P + c];
#pragma unroll
            for (int cc = 0; cc < 4; cc++)
                *(float4*)vb[cc] = *(const float4*)&Vs[(c+cc)*P + tn4];
#pragma unroll
            for (int i = 0; i < 4; i++)
#pragma unroll
                for (int j = 0; j < 4; j++)
                    acc[i][j] += pb[i][0]*vb[0][j] + pb[i][1]*vb[1][j]
                               + pb[i][2]*vb[2][j] + pb[i][3]*vb[3][j];
        }
    }

    // normalize + write
    float linv[4];
#pragma unroll
    for (int i = 0; i < 4; i++) linv[i] = 1.f / lrow[tm4 + i];
#pragma unroll
    for (int i = 0; i < 4; i++){
        float4 o;
        o.x = acc[i][0]*linv[i];
        o.y = acc[i][1]*linv[i];
        o.z = acc[i][2]*linv[i];
        o.w = acc[i][3]*linv[i];
        *(float4*)&Og[base + (size_t)(qt*64 + tm4 + i)*EDIM + tn4] = o;
    }
}

// ---------------- launch ----------------
extern "C" void kernel_launch(void* const* d_in, const int* in_sizes, int n_in,
                              void* d_out, int out_size)
{
    const float* x     = (const float*)d_in[0];
    const float* enc   = (const float*)d_in[1];
    // d_in[2] = tgt_mask: deterministic causal tril, applied analytically
    const float* sa_wq = (const float*)d_in[3];  const float* sa_bq = (const float*)d_in[4];
    const float* sa_wk = (const float*)d_in[5];  const float* sa_bk = (const float*)d_in[6];
    const float* sa_wv = (const float*)d_in[7];  const float* sa_bv = (const float*)d_in[8];
    const float* sa_wo = (const float*)d_in[9];  const float* sa_bo = (const float*)d_in[10];
    const float* ca_wq = (const float*)d_in[11]; const float* ca_bq = (const float*)d_in[12];
    const float* ca_wk = (const float*)d_in[13]; const float* ca_bk = (const float*)d_in[14];
    const float* ca_wv = (const float*)d_in[15]; const float* ca_bv = (const float*)d_in[16];
    const float* ca_wo = (const float*)d_in[17]; const float* ca_bo = (const float*)d_in[18];
    const float* ff_w1 = (const float*)d_in[19]; const float* ff_b1 = (const float*)d_in[20];
    const float* ff_w2 = (const float*)d_in[21]; const float* ff_b2 = (const float*)d_in[22];
    const float* ln1g  = (const float*)d_in[23]; const float* ln1b  = (const float*)d_in[24];
    const float* ln2g  = (const float*)d_in[25]; const float* ln2b  = (const float*)d_in[26];
    const float* ln3g  = (const float*)d_in[27]; const float* ln3b  = (const float*)d_in[28];
    float* out = (float*)d_out;

    float *h, *q, *k, *v, *ao, *x1, *x2, *ff;
    cudaGetSymbolAddress((void**)&h,  g_h);
    cudaGetSymbolAddress((void**)&q,  g_q);
    cudaGetSymbolAddress((void**)&k,  g_kb);
    cudaGetSymbolAddress((void**)&v,  g_vb);
    cudaGetSymbolAddress((void**)&ao, g_ao);
    cudaGetSymbolAddress((void**)&x1, g_x1);
    cudaGetSymbolAddress((void**)&x2, g_x2);
    cudaGetSymbolAddress((void**)&ff, g_ff);

    const int ATTN_SMEM = (4*64*68 + 3*64) * (int)sizeof(float);   // 70400 B
    cudaFuncSetAttribute(attn_kernel<true>,  cudaFuncAttributeMaxDynamicSharedMemorySize, ATTN_SMEM);
    cudaFuncSetAttribute(attn_kernel<false>, cudaFuncAttributeMaxDynamicSharedMemorySize, ATTN_SMEM);

    const dim3 thr(256);
    const dim3 gP (EDIM/128, NTOK/128);    // 8 x 32
    const dim3 gF1(FFD/128,  NTOK/128);    // 32 x 32
    const dim3 gA (TSEQ/64, 16, 2);        // 32 x 16 x 2

    // ---- self attention block ----
    ln_kernel<<<NTOK, 256>>>(x, ln1g, ln1b, h);
    sgemm_kernel<false,false><<<gP, thr>>>(h, sa_wq, sa_bq, nullptr, q, EDIM, EDIM);
    sgemm_kernel<false,false><<<gP, thr>>>(h, sa_wk, sa_bk, nullptr, k, EDIM, EDIM);
    sgemm_kernel<false,false><<<gP, thr>>>(h, sa_wv, sa_bv, nullptr, v, EDIM, EDIM);
    attn_kernel<true><<<gA, thr, ATTN_SMEM>>>(q, k, v, ao);
    sgemm_kernel<false,true ><<<gP, thr>>>(ao, sa_wo, sa_bo, x, x1, EDIM, EDIM);

    // ---- cross attention block ----
    ln_kernel<<<NTOK, 256>>>(x1, ln2g, ln2b, h);
    sgemm_kernel<false,false><<<gP, thr>>>(h,   ca_wq, ca_bq, nullptr, q, EDIM, EDIM);
    sgemm_kernel<false,false><<<gP, thr>>>(enc, ca_wk, ca_bk, nullptr, k, EDIM, EDIM);
    sgemm_kernel<false,false><<<gP, thr>>>(enc, ca_wv, ca_bv, nullptr, v, EDIM, EDIM);
    attn_kernel<false><<<gA, thr, ATTN_SMEM>>>(q, k, v, ao);
    sgemm_kernel<false,true ><<<gP, thr>>>(ao, ca_wo, ca_bo, x1, x2, EDIM, EDIM);

    // ---- feed-forward block ----
    ln_kernel<<<NTOK, 256>>>(x2, ln3g, ln3b, h);
    sgemm_kernel<true ,false><<<gF1, thr>>>(h,  ff_w1, ff_b1, nullptr, ff, FFD, EDIM);
    sgemm_kernel<false,true ><<<gP, thr>>>(ff, ff_w2, ff_b2, x2, out, EDIM, FFD);
}

// round 2
// speedup vs baseline: 2.8331x; 2.8331x over previous
#include <cuda_runtime.h>
#include <math.h>
#include <stdint.h>

#define EDIM 1024
#define TSEQ 2048
#define NTOK 4096      // B * T
#define FFD  4096
#define HDIM 64
#define LN_EPS 1e-5f

// ---------------- scratch (static device globals; no allocation) ----------------
__device__ float g_h [(size_t)NTOK*EDIM];
__device__ float g_q [(size_t)NTOK*EDIM];
__device__ float g_kb[(size_t)NTOK*EDIM];
__device__ float g_vb[(size_t)NTOK*EDIM];
__device__ float g_ao[(size_t)NTOK*EDIM];
__device__ float g_x1[(size_t)NTOK*EDIM];
__device__ float g_x2[(size_t)NTOK*EDIM];
__device__ float g_ff[(size_t)NTOK*FFD];

// ---------------- tf32 helpers ----------------
__device__ __forceinline__ float tf32r(float x){
    uint32_t u; asm("cvt.rna.tf32.f32 %0, %1;" : "=r"(u) : "f"(x));
    return __uint_as_float(u);
}
__device__ __forceinline__ uint32_t tf32u(float x){
    uint32_t u; asm("cvt.rna.tf32.f32 %0, %1;" : "=r"(u) : "f"(x));
    return u;
}
__device__ __forceinline__ void mma_tf32(float* c, const uint32_t* a, uint32_t b0, uint32_t b1){
    asm volatile("mma.sync.aligned.m16n8k8.row.col.f32.tf32.tf32.f32 "
        "{%0,%1,%2,%3}, {%4,%5,%6,%7}, {%8,%9}, {%0,%1,%2,%3};"
        : "+f"(c[0]), "+f"(c[1]), "+f"(c[2]), "+f"(c[3])
        : "r"(a[0]), "r"(a[1]), "r"(a[2]), "r"(a[3]), "r"(b0), "r"(b1));
}

// ---------------- LayerNorm: one block per row of 1024 ----------------
__global__ __launch_bounds__(256)
void ln_kernel(const float* __restrict__ x, const float* __restrict__ gamma,
               const float* __restrict__ beta, float* __restrict__ out)
{
    const int row = blockIdx.x;
    const int t = threadIdx.x;
    const float4 v = ((const float4*)(x + (size_t)row*EDIM))[t];
    float s  = v.x + v.y + v.z + v.w;
    float ss = v.x*v.x + v.y*v.y + v.z*v.z + v.w*v.w;
#pragma unroll
    for (int o = 16; o; o >>= 1){
        s  += __shfl_xor_sync(0xffffffffu, s,  o);
        ss += __shfl_xor_sync(0xffffffffu, ss, o);
    }
    __shared__ float sh_s[8], sh_ss[8];
    const int w = t >> 5, l = t & 31;
    if (l == 0){ sh_s[w] = s; sh_ss[w] = ss; }
    __syncthreads();
    if (w == 0){
        s  = (l < 8) ? sh_s[l]  : 0.f;
        ss = (l < 8) ? sh_ss[l] : 0.f;
#pragma unroll
        for (int o = 4; o; o >>= 1){
            s  += __shfl_xor_sync(0xffffffffu, s,  o);
            ss += __shfl_xor_sync(0xffffffffu, ss, o);
        }
        if (l == 0){ sh_s[0] = s; sh_ss[0] = ss; }
    }
    __syncthreads();
    const float mu   = sh_s[0] * (1.f/EDIM);
    const float var  = sh_ss[0] * (1.f/EDIM) - mu*mu;
    const float rstd = rsqrtf(var + LN_EPS);
    const float4 g4 = ((const float4*)gamma)[t];
    const float4 b4 = ((const float4*)beta)[t];
    float4 o4;
    o4.x = (v.x - mu)*rstd*g4.x + b4.x;
    o4.y = (v.y - mu)*rstd*g4.y + b4.y;
    o4.z = (v.z - mu)*rstd*g4.z + b4.z;
    o4.w = (v.w - mu)*rstd*g4.w + b4.w;
    ((float4*)(out + (size_t)row*EDIM))[t] = o4;
}

// ---------------- TF32 GEMM: C[M,N] = A[M,K] @ W[K,N] + bias (+res)(+relu) ----
// 128x128 block tile, BK=16 double-buffered, 256 thr = 8 warps (4m x 2n),
// warp tile 32x64 = 2 m-atoms x 8 n-atoms of mma.m16n8k8.tf32.
template<bool RELU, bool RES>
__global__ __launch_bounds__(256)
void gemm_tf32(const float* __restrict__ A, const float* __restrict__ W,
               const float* __restrict__ bias, const float* __restrict__ res,
               float* __restrict__ C, int N, int K)
{
    __shared__ float As[2][128][20];    // [m][k], stride 20 -> conflict-free frags
    __shared__ float Bs[2][16][136];    // [k][n], stride 136 -> conflict-free frags

    const int tid  = threadIdx.x;
    const int lane = tid & 31;
    const int wid  = tid >> 5;
    const int gid  = lane >> 2;      // 0..7
    const int tig  = lane & 3;       // 0..3
    const int wm   = (wid & 3) * 32; // warp row base in tile
    const int wn   = (wid >> 2) * 64;// warp col base in tile
    const int m0 = blockIdx.y * 128;
    const int n0 = blockIdx.x * 128;

    // gmem->smem mapping (2 float4 of A, 2 float4 of B per thread per stage)
    const int a_row = tid >> 2;          // 0..63 (and +64)
    const int a_col = (tid & 3) * 4;     // 0,4,8,12
    const int b_row = tid >> 5;          // 0..7 (and +8)
    const int b_col = (tid & 31) * 4;    // 0..124
    const float* Ap0 = A + (size_t)(m0 + a_row)*K + a_col;
    const float* Ap1 = A + (size_t)(m0 + a_row + 64)*K + a_col;
    const float* Wp0 = W + (size_t)b_row*N + n0 + b_col;
    const float* Wp1 = W + (size_t)(b_row + 8)*N + n0 + b_col;

    float acc[2][8][4];
#pragma unroll
    for (int i = 0; i < 2; i++)
#pragma unroll
        for (int j = 0; j < 8; j++)
#pragma unroll
            for (int k = 0; k < 4; k++) acc[i][j][k] = 0.f;

    // prologue: fill stage 0
    {
        float4 a0 = *(const float4*)Ap0;
        float4 a1 = *(const float4*)Ap1;
        float4 b0 = *(const float4*)Wp0;
        float4 b1 = *(const float4*)Wp1;
        float4 t;
        t.x=tf32r(a0.x); t.y=tf32r(a0.y); t.z=tf32r(a0.z); t.w=tf32r(a0.w);
        *(float4*)&As[0][a_row][a_col] = t;
        t.x=tf32r(a1.x); t.y=tf32r(a1.y); t.z=tf32r(a1.z); t.w=tf32r(a1.w);
        *(float4*)&As[0][a_row+64][a_col] = t;
        t.x=tf32r(b0.x); t.y=tf32r(b0.y); t.z=tf32r(b0.z); t.w=tf32r(b0.w);
        *(float4*)&Bs[0][b_row][b_col] = t;
        t.x=tf32r(b1.x); t.y=tf32r(b1.y); t.z=tf32r(b1.z); t.w=tf32r(b1.w);
        *(float4*)&Bs[0][b_row+8][b_col] = t;
    }

    const int KT = K >> 4;
    for (int kt = 0; kt < KT; ++kt){
        __syncthreads();
        const int buf = kt & 1;
        float4 na0, na1, nb0, nb1;
        const bool more = (kt + 1 < KT);
        if (more){
            const int ko = (kt + 1) * 16;
            na0 = *(const float4*)(Ap0 + ko);
            na1 = *(const float4*)(Ap1 + ko);
            nb0 = *(const float4*)(Wp0 + (size_t)ko*N);
            nb1 = *(const float4*)(Wp1 + (size_t)ko*N);
        }
#pragma unroll
        for (int kk = 0; kk < 16; kk += 8){
            uint32_t afr[2][4];
#pragma unroll
            for (int ma = 0; ma < 2; ma++){
                const int r = wm + ma*16 + gid;
                afr[ma][0] = __float_as_uint(As[buf][r    ][kk + tig]);
                afr[ma][1] = __float_as_uint(As[buf][r + 8][kk + tig]);
                afr[ma][2] = __float_as_uint(As[buf][r    ][kk + tig + 4]);
                afr[ma][3] = __float_as_uint(As[buf][r + 8][kk + tig + 4]);
            }
#pragma unroll
            for (int na = 0; na < 8; na++){
                const int c = wn + na*8 + gid;
                const uint32_t b0 = __float_as_uint(Bs[buf][kk + tig    ][c]);
                const uint32_t b1 = __float_as_uint(Bs[buf][kk + tig + 4][c]);
                mma_tf32(acc[0][na], afr[0], b0, b1);
                mma_tf32(acc[1][na], afr[1], b0, b1);
            }
        }
        if (more){
            const int nxt = buf ^ 1;
            float4 t;
            t.x=tf32r(na0.x); t.y=tf32r(na0.y); t.z=tf32r(na0.z); t.w=tf32r(na0.w);
            *(float4*)&As[nxt][a_row][a_col] = t;
            t.x=tf32r(na1.x); t.y=tf32r(na1.y); t.z=tf32r(na1.z); t.w=tf32r(na1.w);
            *(float4*)&As[nxt][a_row+64][a_col] = t;
            t.x=tf32r(nb0.x); t.y=tf32r(nb0.y); t.z=tf32r(nb0.z); t.w=tf32r(nb0.w);
            *(float4*)&Bs[nxt][b_row][b_col] = t;
            t.x=tf32r(nb1.x); t.y=tf32r(nb1.y); t.z=tf32r(nb1.z); t.w=tf32r(nb1.w);
            *(float4*)&Bs[nxt][b_row+8][b_col] = t;
        }
    }

    // epilogue: accum layout c0,c1 -> row r, cols 2*tig,2*tig+1; c2,c3 -> row r+8
#pragma unroll
    for (int ma = 0; ma < 2; ma++){
        const int r0 = m0 + wm + ma*16 + gid;
        const int r1 = r0 + 8;
#pragma unroll
        for (int na = 0; na < 8; na++){
            const int c = n0 + wn + na*8 + 2*tig;
            const float2 bb = *(const float2*)&bias[c];
            float v00 = acc[ma][na][0] + bb.x;
            float v01 = acc[ma][na][1] + bb.y;
            float v10 = acc[ma][na][2] + bb.x;
            float v11 = acc[ma][na][3] + bb.y;
            if (RELU){
                v00 = fmaxf(v00, 0.f); v01 = fmaxf(v01, 0.f);
                v10 = fmaxf(v10, 0.f); v11 = fmaxf(v11, 0.f);
            }
            if (RES){
                const float2 r0v = *(const float2*)&res[(size_t)r0*N + c];
                const float2 r1v = *(const float2*)&res[(size_t)r1*N + c];
                v00 += r0v.x; v01 += r0v.y; v10 += r1v.x; v11 += r1v.y;
            }
            float2 o0; o0.x = v00; o0.y = v01;
            float2 o1; o1.x = v10; o1.y = v11;
            *(float2*)&C[(size_t)r0*N + c] = o0;
            *(float2*)&C[(size_t)r1*N + c] = o1;
        }
    }
}

// ---------------- Flash attention, TF32 mma + fp32 online softmax ----------------
// Block = 64 queries x 64 head dims for one (b,h); key tiles of 64.
// 8 warps (4m x 2n): warp tile S = 16x32 (4 n-atoms), O = 16x32 dims.
template<bool CAUSAL>
__global__ __launch_bounds__(256)
void attn_tf32(const float* __restrict__ Qg, const float* __restrict__ Kg,
               const float* __restrict__ Vg, float* __restrict__ Og)
{
    const int AP = 76;                   // row stride: conflict-free for all frags
    extern __shared__ float sm[];
    float* Qs   = sm;                    // [64][76] tf32
    float* Ks   = Qs + 64*AP;            // [64][76] tf32
    float* Vs   = Ks + 64*AP;            // [64][76] tf32
    float* Ss   = Vs + 64*AP;            // [64][76] fp32 scores / probs
    float* mrow = Ss + 64*AP;
    float* lrow = mrow + 64;
    float* arow = lrow + 64;

    const int tid  = threadIdx.x;
    const int lane = tid & 31;
    const int wid  = tid >> 5;
    const int gid  = lane >> 2;
    const int tig  = lane & 3;
    const int wm   = (wid & 3) * 16;     // 4 m-warps x 16 rows
    const int wn   = (wid >> 2) * 32;    // 2 n-warps x 32 cols
    const int qt = blockIdx.x, h = blockIdx.y, b = blockIdx.z;
    const size_t base = (size_t)b*TSEQ*EDIM + (size_t)h*HDIM;

    // load Q tile (convert to tf32 once)
#pragma unroll
    for (int i = 0; i < 4; i++){
        const int t4 = tid + i*256;
        const int r = t4 >> 4;
        const int c = (t4 & 15) << 2;
        const float4 v = *(const float4*)&Qg[base + (size_t)(qt*64 + r)*EDIM + c];
        Qs[r*AP + c + 0] = tf32r(v.x);
        Qs[r*AP + c + 1] = tf32r(v.y);
        Qs[r*AP + c + 2] = tf32r(v.z);
        Qs[r*AP + c + 3] = tf32r(v.w);
    }
    if (tid < 64){ mrow[tid] = -1e30f; lrow[tid] = 0.f; }

    float oacc[4][4];
#pragma unroll
    for (int i = 0; i < 4; i++)
#pragma unroll
        for (int j = 0; j < 4; j++) oacc[i][j] = 0.f;

    const int nkt = CAUSAL ? (qt + 1) : (TSEQ/64);

    for (int kt = 0; kt < nkt; ++kt){
        __syncthreads();
#pragma unroll
        for (int i = 0; i < 4; i++){
            const int t4 = tid + i*256;
            const int r = t4 >> 4;
            const int c = (t4 & 15) << 2;
            const size_t go = base + (size_t)(kt*64 + r)*EDIM + c;
            const float4 kv = *(const float4*)&Kg[go];
            const float4 vv = *(const float4*)&Vg[go];
            Ks[r*AP + c + 0] = tf32r(kv.x);
            Ks[r*AP + c + 1] = tf32r(kv.y);
            Ks[r*AP + c + 2] = tf32r(kv.z);
            Ks[r*AP + c + 3] = tf32r(kv.w);
            Vs[r*AP + c + 0] = tf32r(vv.x);
            Vs[r*AP + c + 1] = tf32r(vv.y);
            Vs[r*AP + c + 2] = tf32r(vv.z);
            Vs[r*AP + c + 3] = tf32r(vv.w);
        }
        __syncthreads();

        // ---- S = Q K^T (warp: 16x32 via 4 n-atoms, K over d in 8-chunks) ----
        float sa[4][4];
#pragma unroll
        for (int na = 0; na < 4; na++)
#pragma unroll
            for (int k = 0; k < 4; k++) sa[na][k] = 0.f;
#pragma unroll
        for (int d8 = 0; d8 < 8; d8++){
            const int d = d8 * 8;
            uint32_t afr[4];
            afr[0] = __float_as_uint(Qs[(wm + gid    )*AP + d + tig]);
            afr[1] = __float_as_uint(Qs[(wm + gid + 8)*AP + d + tig]);
            afr[2] = __float_as_uint(Qs[(wm + gid    )*AP + d + tig + 4]);
            afr[3] = __float_as_uint(Qs[(wm + gid + 8)*AP + d + tig + 4]);
#pragma unroll
            for (int na = 0; na < 4; na++){
                const int kr = wn + na*8 + gid;
                const uint32_t b0 = __float_as_uint(Ks[kr*AP + d + tig]);
                const uint32_t b1 = __float_as_uint(Ks[kr*AP + d + tig + 4]);
                mma_tf32(sa[na], afr, b0, b1);
            }
        }
        // scale + causal mask + store to Ss
        {
            const int r0 = wm + gid;
            const int r1 = r0 + 8;
            const int gr0 = qt*64 + r0;
            const int gr1 = qt*64 + r1;
#pragma unroll
            for (int na = 0; na < 4; na++){
                const int col = wn + na*8 + 2*tig;
                const int gc  = kt*64 + col;
                float v00 = sa[na][0] * 0.125f;
                float v01 = sa[na][1] * 0.125f;
                float v10 = sa[na][2] * 0.125f;
                float v11 = sa[na][3] * 0.125f;
                if (CAUSAL){
                    if (gc     > gr0) v00 = -1e30f;
                    if (gc + 1 > gr0) v01 = -1e30f;
                    if (gc     > gr1) v10 = -1e30f;
                    if (gc + 1 > gr1) v11 = -1e30f;
                }
                float2 s0; s0.x = v00; s0.y = v01;
                float2 s1; s1.x = v10; s1.y = v11;
                *(float2*)&Ss[r0*AP + col] = s0;
                *(float2*)&Ss[r1*AP + col] = s1;
            }
        }
        __syncthreads();

        // ---- online softmax: 4 lanes per row, 16 cols each ----
        {
            const int r = tid >> 2;
            const int g = tid & 3;
            float* srow = &Ss[r*AP + g*16];
            const float mold = mrow[r];
            float mx = -1e30f;
#pragma unroll
            for (int c = 0; c < 16; c++) mx = fmaxf(mx, srow[c]);
            mx = fmaxf(mx, __shfl_xor_sync(0xffffffffu, mx, 1));
            mx = fmaxf(mx, __shfl_xor_sync(0xffffffffu, mx, 2));
            const float mnew = fmaxf(mold, mx);
            float sum = 0.f;
#pragma unroll
            for (int c = 0; c < 16; c++){
                const float p = __expf(srow[c] - mnew);
                srow[c] = p;
                sum += p;
            }
            sum += __shfl_xor_sync(0xffffffffu, sum, 1);
            sum += __shfl_xor_sync(0xffffffffu, sum, 2);
            if (g == 0){
                const float al = __expf(mold - mnew);
                mrow[r] = mnew;
                lrow[r] = lrow[r]*al + sum;
                arow[r] = al;
            }
        }
        __syncthreads();

        // ---- O = O*alpha + P @ V ----
        const float al0 = arow[wm + gid];
        const float al1 = arow[wm + gid + 8];
#pragma unroll
        for (int na = 0; na < 4; na++){
            oacc[na][0] *= al0; oacc[na][1] *= al0;
            oacc[na][2] *= al1; oacc[na][3] *= al1;
        }
#pragma unroll
        for (int k8 = 0; k8 < 8; k8++){
            const int kk = k8 * 8;
            uint32_t afr[4];
            afr[0] = tf32u(Ss[(wm + gid    )*AP + kk + tig]);
            afr[1] = tf32u(Ss[(wm + gid + 8)*AP + kk + tig]);
            afr[2] = tf32u(Ss[(wm + gid    )*AP + kk + tig + 4]);
            afr[3] = tf32u(Ss[(wm + gid + 8)*AP + kk + tig + 4]);
#pragma unroll
            for (int na = 0; na < 4; na++){
                const int dc = wn + na*8 + gid;
                const uint32_t b0 = __float_as_uint(Vs[(kk + tig    )*AP + dc]);
                const uint32_t b1 = __float_as_uint(Vs[(kk + tig + 4)*AP + dc]);
                mma_tf32(oacc[na], afr, b0, b1);
            }
        }
    }

    // normalize + write (float2 per row pair)
    const float li0 = 1.f / lrow[wm + gid];
    const float li1 = 1.f / lrow[wm + gid + 8];
    const int row0 = qt*64 + wm + gid;
    const int row1 = row0 + 8;
#pragma unroll
    for (int na = 0; na < 4; na++){
        const int col = wn + na*8 + 2*tig;
        float2 o0; o0.x = oacc[na][0]*li0; o0.y = oacc[na][1]*li0;
        float2 o1; o1.x = oacc[na][2]*li1; o1.y = oacc[na][3]*li1;
        *(float2*)&Og[base + (size_t)row0*EDIM + col] = o0;
        *(float2*)&Og[base + (size_t)row1*EDIM + col] = o1;
    }
}

// ---------------- launch ----------------
extern "C" void kernel_launch(void* const* d_in, const int* in_sizes, int n_in,
                              void* d_out, int out_size)
{
    const float* x     = (const float*)d_in[0];
    const float* enc   = (const float*)d_in[1];
    // d_in[2] = tgt_mask: deterministic causal tril, applied analytically
    const float* sa_wq = (const float*)d_in[3];  const float* sa_bq = (const float*)d_in[4];
    const float* sa_wk = (const float*)d_in[5];  const float* sa_bk = (const float*)d_in[6];
    const float* sa_wv = (const float*)d_in[7];  const float* sa_bv = (const float*)d_in[8];
    const float* sa_wo = (const float*)d_in[9];  const float* sa_bo = (const float*)d_in[10];
    const float* ca_wq = (const float*)d_in[11]; const float* ca_bq = (const float*)d_in[12];
    const float* ca_wk = (const float*)d_in[13]; const float* ca_bk = (const float*)d_in[14];
    const float* ca_wv = (const float*)d_in[15]; const float* ca_bv = (const float*)d_in[16];
    const float* ca_wo = (const float*)d_in[17]; const float* ca_bo = (const float*)d_in[18];
    const float* ff_w1 = (const float*)d_in[19]; const float* ff_b1 = (const float*)d_in[20];
    const float* ff_w2 = (const float*)d_in[21]; const float* ff_b2 = (const float*)d_in[22];
    const float* ln1g  = (const float*)d_in[23]; const float* ln1b  = (const float*)d_in[24];
    const float* ln2g  = (const float*)d_in[25]; const float* ln2b  = (const float*)d_in[26];
    const float* ln3g  = (const float*)d_in[27]; const float* ln3b  = (const float*)d_in[28];
    float* out = (float*)d_out;

    float *h, *q, *k, *v, *ao, *x1, *x2, *ff;
    cudaGetSymbolAddress((void**)&h,  g_h);
    cudaGetSymbolAddress((void**)&q,  g_q);
    cudaGetSymbolAddress((void**)&k,  g_kb);
    cudaGetSymbolAddress((void**)&v,  g_vb);
    cudaGetSymbolAddress((void**)&ao, g_ao);
    cudaGetSymbolAddress((void**)&x1, g_x1);
    cudaGetSymbolAddress((void**)&x2, g_x2);
    cudaGetSymbolAddress((void**)&ff, g_ff);

    const int ATTN_SMEM = (4*64*76 + 3*64) * (int)sizeof(float);   // 78592 B
    cudaFuncSetAttribute(attn_tf32<true>,  cudaFuncAttributeMaxDynamicSharedMemorySize, ATTN_SMEM);
    cudaFuncSetAttribute(attn_tf32<false>, cudaFuncAttributeMaxDynamicSharedMemorySize, ATTN_SMEM);

    const dim3 thr(256);
    const dim3 gP (EDIM/128, NTOK/128);    // 8 x 32
    const dim3 gF1(FFD/128,  NTOK/128);    // 32 x 32
    const dim3 gA (TSEQ/64, 16, 2);        // 32 x 16 x 2

    // ---- self attention block ----
    ln_kernel<<<NTOK, 256>>>(x, ln1g, ln1b, h);
    gemm_tf32<false,false><<<gP, thr>>>(h, sa_wq, sa_bq, nullptr, q, EDIM, EDIM);
    gemm_tf32<false,false><<<gP, thr>>>(h, sa_wk, sa_bk, nullptr, k, EDIM, EDIM);
    gemm_tf32<false,false><<<gP, thr>>>(h, sa_wv, sa_bv, nullptr, v, EDIM, EDIM);
    attn_tf32<true><<<gA, thr, ATTN_SMEM>>>(q, k, v, ao);
    gemm_tf32<false,true ><<<gP, thr>>>(ao, sa_wo, sa_bo, x, x1, EDIM, EDIM);

    // ---- cross attention block ----
    ln_kernel<<<NTOK, 256>>>(x1, ln2g, ln2b, h);
    gemm_tf32<false,false><<<gP, thr>>>(h,   ca_wq, ca_bq, nullptr, q, EDIM, EDIM);
    gemm_tf32<false,false><<<gP, thr>>>(enc, ca_wk, ca_bk, nullptr, k, EDIM, EDIM);
    gemm_tf32<false,false><<<gP, thr>>>(enc, ca_wv, ca_bv, nullptr, v, EDIM, EDIM);
    attn_tf32<false><<<gA, thr, ATTN_SMEM>>>(q, k, v, ao);
    gemm_tf32<false,true ><<<gP, thr>>>(ao, ca_wo, ca_bo, x1, x2, EDIM, EDIM);

    // ---- feed-forward block ----
    ln_kernel<<<NTOK, 256>>>(x2, ln3g, ln3b, h);
    gemm_tf32<true ,false><<<gF1, thr>>>(h,  ff_w1, ff_b1, nullptr, ff, FFD, EDIM);
    gemm_tf32<false,true ><<<gP, thr>>>(ff, ff_w2, ff_b2, x2, out, EDIM, FFD);
}